// round 13
// baseline (speedup 1.0000x reference)
#include <cuda_runtime.h>
#include <cuda_fp16.h>

#define NN 50000
#define EE 800000
#define ET 850000          // EE + NN self loops
#define GG 50
#define FIN 64
#define HID 128
#define EMB 64
#define H1 8
#define C1 16
#define NCLS 6
#define EPSV 1e-5f
#define SLOPE 0.2f
#define NB 196

// ---------------- scratch ----------------
__device__ int    g_ideg[NN], g_fill[NN], g_rowstart[NN];
__device__ int    g_psum[NB], g_poff[NB];
__device__ int2   g_edge[ET];          // {src, attr bits}
__device__ float  g_asum[NN];
__device__ __half g_xl1h[NN * HID];
__device__ float  g_xr1[NN * HID], g_out1[NN * HID];
__device__ float  g_xl2[NN * EMB], g_xr2[NN * EMB], g_out2[NN * EMB];
__device__ float  g_bnsum[HID], g_bnsq[HID];
__device__ float  g_bnsum2[EMB], g_bnsq2[EMB];
__device__ float  g_pool[GG * EMB], g_cnt[GG], g_dom[GG * EMB];

// ---------------- streams (static init; no device memory alloc) ----------------
static cudaStream_t g_side = nullptr;
static cudaEvent_t g_evF = nullptr, g_evJ = nullptr;
static struct SInit {
    SInit() {
        if (cudaStreamCreateWithFlags(&g_side, cudaStreamNonBlocking) != cudaSuccess) {
            g_side = nullptr; return;
        }
        if (cudaEventCreateWithFlags(&g_evF, cudaEventDisableTiming) != cudaSuccess ||
            cudaEventCreateWithFlags(&g_evJ, cudaEventDisableTiming) != cudaSuccess) {
            g_side = nullptr;
        }
    }
} s_init;

// ---------------- setup kernels ----------------
__global__ void k_zero() {
    int i = blockIdx.x * blockDim.x + threadIdx.x;
    if (i < NN) { g_ideg[i] = 0; g_fill[i] = 0; g_asum[i] = 0.f; }
    if (i < HID) { g_bnsum[i] = 0.f; g_bnsq[i] = 0.f; }
    if (i < EMB) { g_bnsum2[i] = 0.f; g_bnsq2[i] = 0.f; }
    if (i < GG * EMB) g_pool[i] = 0.f;
    if (i < GG) g_cnt[i] = 0.f;
}

__global__ void k_hist(const int* __restrict__ dst, const float* __restrict__ eattr) {
    int i = blockIdx.x * blockDim.x + threadIdx.x;
    if (i >= EE) return;
    int d = dst[i];
    atomicAdd(&g_ideg[d], 1);
    atomicAdd(&g_asum[d], eattr[i]);
}

__global__ void k_scanA() {
    __shared__ int s[256];
    int i = blockIdx.x * 256 + threadIdx.x;
    int v = (i < NN) ? g_ideg[i] + 1 : 0;
    s[threadIdx.x] = v; __syncthreads();
    for (int off = 128; off > 0; off >>= 1) {
        if (threadIdx.x < off) s[threadIdx.x] += s[threadIdx.x + off];
        __syncthreads();
    }
    if (threadIdx.x == 0) g_psum[blockIdx.x] = s[0];
}

__global__ void k_scanB() {
    __shared__ int s[256];
    int t = threadIdx.x;
    int v = (t < NB) ? g_psum[t] : 0;
    s[t] = v; __syncthreads();
    for (int off = 1; off < 256; off <<= 1) {
        int x = (t >= off) ? s[t - off] : 0;
        __syncthreads();
        s[t] += x;
        __syncthreads();
    }
    if (t < NB) g_poff[t] = s[t] - v;
}

// per-block exclusive scan + rowstart + self-loop record + batch counts
__global__ void k_scanC(const int* __restrict__ batch) {
    __shared__ int s[256];
    int t = threadIdx.x;
    int i = blockIdx.x * 256 + t;
    int deg = (i < NN) ? g_ideg[i] : 0;
    int v = (i < NN) ? deg + 1 : 0;
    s[t] = v; __syncthreads();
    for (int off = 1; off < 256; off <<= 1) {
        int x = (t >= off) ? s[t - off] : 0;
        __syncthreads();
        s[t] += x;
        __syncthreads();
    }
    if (i < NN) {
        int rs = g_poff[blockIdx.x] + s[t] - v;
        g_rowstart[i] = rs;
        float la = deg > 0 ? g_asum[i] / (float)deg : 0.f;
        g_edge[rs + deg] = make_int2(i, __float_as_int(la));   // self loop last
        atomicAdd(&g_cnt[batch[i]], 1.f);
    }
}

__global__ void k_scatterE(const int* __restrict__ src, const int* __restrict__ dst,
                           const float* __restrict__ eattr) {
    int e = blockIdx.x * blockDim.x + threadIdx.x;
    if (e >= EE) return;
    int d = dst[e];
    int pos = g_rowstart[d] + atomicAdd(&g_fill[d], 1);
    g_edge[pos] = make_int2(src[e], __float_as_int(eattr[e]));
}

// ---------------- tensor-core GEMM: mma.sync m16n8k16 fp16->fp32 -------------
#define LDSM_X4(r0, r1, r2, r3, addr) \
    asm volatile("ldmatrix.sync.aligned.m8n8.x4.shared.b16 {%0,%1,%2,%3}, [%4];" \
        : "=r"(r0), "=r"(r1), "=r"(r2), "=r"(r3) : "r"(addr))
#define LDSM_X4_T(r0, r1, r2, r3, addr) \
    asm volatile("ldmatrix.sync.aligned.m8n8.x4.trans.shared.b16 {%0,%1,%2,%3}, [%4];" \
        : "=r"(r0), "=r"(r1), "=r"(r2), "=r"(r3) : "r"(addr))
#define MMA16816(d, a0, a1, a2, a3, b0, b1) \
    asm volatile("mma.sync.aligned.m16n8k16.row.col.f32.f16.f16.f32 " \
        "{%0,%1,%2,%3}, {%4,%5,%6,%7}, {%8,%9}, {%0,%1,%2,%3};" \
        : "+f"((d)[0]), "+f"((d)[1]), "+f"((d)[2]), "+f"((d)[3]) \
        : "r"(a0), "r"(a1), "r"(a2), "r"(a3), "r"(b0), "r"(b1))

template<int KIN, bool BNF, bool HOUT>
__global__ void k_gemm(const float* __restrict__ X,
                       const float* __restrict__ W1, const float* __restrict__ b1,
                       float* __restrict__ Y1, __half* __restrict__ Y1h,
                       const float* __restrict__ W2, const float* __restrict__ b2,
                       float* __restrict__ Y2,
                       int kout, int tiles1,
                       const float* __restrict__ gamma, const float* __restrict__ beta) {
    __shared__ __half As[128][72];
    __shared__ __half Bs[64][72];
    __shared__ float sscale[128], sshift[128];
    int tid = threadIdx.x;
    if (BNF) {
        if (tid < KIN) {
            float mu = g_bnsum[tid] * (1.f / NN);
            float var = g_bnsq[tid] * (1.f / NN) - mu * mu;
            float sc = gamma[tid] * rsqrtf(var + EPSV);
            sscale[tid] = sc;
            sshift[tid] = beta[tid] - mu * sc;
        }
        __syncthreads();
    }
    int yt = blockIdx.y;
    bool first = yt < tiles1;
    const float* W; const float* bb; int colbase;
    if (first) { W = W1; bb = b1; colbase = yt * 64; }
    else       { W = W2; bb = b2; colbase = (yt - tiles1) * 64; }

    int warp = tid >> 5, lane = tid & 31;
    int wm = warp & 3, wn = warp >> 2;
    int r0 = blockIdx.x * 128;
    float acc[2][4][4] = {};

#pragma unroll
    for (int kc = 0; kc < KIN / 64; kc++) {
#pragma unroll
        for (int it = 0; it < 8; it++) {
            int idx = tid + it * 256;
            int row = idx >> 4, c4 = (idx & 15) * 4;
            int grow = r0 + row;
            float4 v = {0.f, 0.f, 0.f, 0.f};
            if (grow < NN)
                v = *(const float4*)(X + (size_t)grow * KIN + kc * 64 + c4);
            if (BNF) {
                int ka = kc * 64 + c4;
                v.x = fmaxf(fmaf(v.x, sscale[ka + 0], sshift[ka + 0]), 0.f);
                v.y = fmaxf(fmaf(v.y, sscale[ka + 1], sshift[ka + 1]), 0.f);
                v.z = fmaxf(fmaf(v.z, sscale[ka + 2], sshift[ka + 2]), 0.f);
                v.w = fmaxf(fmaf(v.w, sscale[ka + 3], sshift[ka + 3]), 0.f);
            }
            *(__half2*)&As[row][c4]     = __floats2half2_rn(v.x, v.y);
            *(__half2*)&As[row][c4 + 2] = __floats2half2_rn(v.z, v.w);
        }
#pragma unroll
        for (int it = 0; it < 4; it++) {
            int idx = tid + it * 256;
            int k = idx >> 4, c4 = (idx & 15) * 4;
            float4 v = *(const float4*)(W + (size_t)(kc * 64 + k) * kout + colbase + c4);
            *(__half2*)&Bs[k][c4]     = __floats2half2_rn(v.x, v.y);
            *(__half2*)&Bs[k][c4 + 2] = __floats2half2_rn(v.z, v.w);
        }
        __syncthreads();
#pragma unroll
        for (int ks = 0; ks < 4; ks++) {
            int k0 = ks * 16;
            unsigned a[2][4], b[2][4];
            int arow_base = wm * 32 + ((lane & 7) + 8 * ((lane >> 3) & 1));
            int acol = k0 + 8 * (lane >> 4);
#pragma unroll
            for (int mt = 0; mt < 2; mt++) {
                unsigned addr = (unsigned)__cvta_generic_to_shared(
                    &As[arow_base + mt * 16][acol]);
                LDSM_X4(a[mt][0], a[mt][1], a[mt][2], a[mt][3], addr);
            }
            int krow = k0 + (lane & 7) + 8 * ((lane >> 3) & 1);
#pragma unroll
            for (int np = 0; np < 2; np++) {
                int ncol = wn * 32 + np * 16 + 8 * (lane >> 4);
                unsigned addr = (unsigned)__cvta_generic_to_shared(&Bs[krow][ncol]);
                LDSM_X4_T(b[np][0], b[np][1], b[np][2], b[np][3], addr);
            }
#pragma unroll
            for (int mt = 0; mt < 2; mt++)
#pragma unroll
                for (int nt = 0; nt < 4; nt++) {
                    unsigned b0 = b[nt >> 1][(nt & 1) * 2 + 0];
                    unsigned b1 = b[nt >> 1][(nt & 1) * 2 + 1];
                    MMA16816(acc[mt][nt], a[mt][0], a[mt][1], a[mt][2], a[mt][3], b0, b1);
                }
        }
        __syncthreads();
    }

    int gID = lane >> 2, tig = lane & 3;
#pragma unroll
    for (int mt = 0; mt < 2; mt++)
#pragma unroll
        for (int nt = 0; nt < 4; nt++) {
            int col = colbase + wn * 32 + nt * 8 + tig * 2;
            float bias0 = bb[col], bias1 = bb[col + 1];
#pragma unroll
            for (int hrow = 0; hrow < 2; hrow++) {
                int row = r0 + wm * 32 + mt * 16 + gID + hrow * 8;
                if (row < NN) {
                    float o0 = acc[mt][nt][hrow * 2 + 0] + bias0;
                    float o1 = acc[mt][nt][hrow * 2 + 1] + bias1;
                    if (HOUT && first) {
                        *(__half2*)(Y1h + (size_t)row * kout + col) =
                            __floats2half2_rn(o0, o1);
                    } else {
                        float* Y = first ? Y1 : Y2;
                        float2 o = {o0, o1};
                        *(float2*)(Y + (size_t)row * kout + col) = o;
                    }
                }
            }
        }
}

// ---------------- fused GATv2 aggregation + BN stats ------------------------
// warp/node, 4-edge batch, edge-record prefetch pipeline (records of batch i+1
// load while batch i's gathers are in flight).
__device__ __forceinline__ void xl1_load(int s, int c0, float4& f) {
    uint2 raw = *(const uint2*)(g_xl1h + (size_t)s * HID + c0);
    float2 f01 = __half22float2(*(__half2*)&raw.x);
    float2 f23 = __half22float2(*(__half2*)&raw.y);
    f.x = f01.x; f.y = f01.y; f.z = f23.x; f.w = f23.y;
}

__global__ void k_agg1(const float* __restrict__ We, const float* __restrict__ att) {
    __shared__ float ssum[HID], ssq[HID];
    int t = threadIdx.x;
    if (t < HID) { ssum[t] = 0.f; ssq[t] = 0.f; }
    __syncthreads();
    int n = (blockIdx.x * blockDim.x + t) >> 5;
    int lane = t & 31;
    int start = g_rowstart[n];
    int end = start + g_ideg[n] + 1;
    int c0 = lane * 4;
    float4 xr = *(const float4*)(g_xr1 + (size_t)n * HID + c0);
    float4 we = *(const float4*)(We + c0);
    int h = lane >> 2;
    float4 at = *(const float4*)(att + h * C1 + (lane & 3) * 4);
    float4 numA = {0.f, 0.f, 0.f, 0.f}, numB = {0.f, 0.f, 0.f, 0.f};
    float denA = 0.f, denB = 0.f;
    int e = start;
    int2 r0, r1, r2, r3;
    if (e + 3 < end) {
        r0 = g_edge[e]; r1 = g_edge[e + 1]; r2 = g_edge[e + 2]; r3 = g_edge[e + 3];
    }
    while (e + 3 < end) {
        int s0 = r0.x, s1 = r1.x, s2 = r2.x, s3 = r3.x;
        float a0 = __int_as_float(r0.y), a1 = __int_as_float(r1.y);
        float a2 = __int_as_float(r2.y), a3 = __int_as_float(r3.y);
        float4 x0, x1, x2, x3;
        xl1_load(s0, c0, x0);
        xl1_load(s1, c0, x1);
        xl1_load(s2, c0, x2);
        xl1_load(s3, c0, x3);
        int en = e + 4;
        if (en + 3 < end) {   // prefetch next batch's records
            r0 = g_edge[en]; r1 = g_edge[en + 1]; r2 = g_edge[en + 2]; r3 = g_edge[en + 3];
        }
        float u0, u1, u2, u3;
        u0 = x0.x + xr.x + a0 * we.x; u0 = u0 > 0.f ? u0 : SLOPE * u0;
        u1 = x0.y + xr.y + a0 * we.y; u1 = u1 > 0.f ? u1 : SLOPE * u1;
        u2 = x0.z + xr.z + a0 * we.z; u2 = u2 > 0.f ? u2 : SLOPE * u2;
        u3 = x0.w + xr.w + a0 * we.w; u3 = u3 > 0.f ? u3 : SLOPE * u3;
        float p0 = u0 * at.x + u1 * at.y + u2 * at.z + u3 * at.w;
        u0 = x1.x + xr.x + a1 * we.x; u0 = u0 > 0.f ? u0 : SLOPE * u0;
        u1 = x1.y + xr.y + a1 * we.y; u1 = u1 > 0.f ? u1 : SLOPE * u1;
        u2 = x1.z + xr.z + a1 * we.z; u2 = u2 > 0.f ? u2 : SLOPE * u2;
        u3 = x1.w + xr.w + a1 * we.w; u3 = u3 > 0.f ? u3 : SLOPE * u3;
        float p1 = u0 * at.x + u1 * at.y + u2 * at.z + u3 * at.w;
        u0 = x2.x + xr.x + a2 * we.x; u0 = u0 > 0.f ? u0 : SLOPE * u0;
        u1 = x2.y + xr.y + a2 * we.y; u1 = u1 > 0.f ? u1 : SLOPE * u1;
        u2 = x2.z + xr.z + a2 * we.z; u2 = u2 > 0.f ? u2 : SLOPE * u2;
        u3 = x2.w + xr.w + a2 * we.w; u3 = u3 > 0.f ? u3 : SLOPE * u3;
        float p2 = u0 * at.x + u1 * at.y + u2 * at.z + u3 * at.w;
        u0 = x3.x + xr.x + a3 * we.x; u0 = u0 > 0.f ? u0 : SLOPE * u0;
        u1 = x3.y + xr.y + a3 * we.y; u1 = u1 > 0.f ? u1 : SLOPE * u1;
        u2 = x3.z + xr.z + a3 * we.z; u2 = u2 > 0.f ? u2 : SLOPE * u2;
        u3 = x3.w + xr.w + a3 * we.w; u3 = u3 > 0.f ? u3 : SLOPE * u3;
        float p3 = u0 * at.x + u1 * at.y + u2 * at.z + u3 * at.w;
        p0 += __shfl_xor_sync(0xffffffffu, p0, 1);
        p1 += __shfl_xor_sync(0xffffffffu, p1, 1);
        p2 += __shfl_xor_sync(0xffffffffu, p2, 1);
        p3 += __shfl_xor_sync(0xffffffffu, p3, 1);
        p0 += __shfl_xor_sync(0xffffffffu, p0, 2);
        p1 += __shfl_xor_sync(0xffffffffu, p1, 2);
        p2 += __shfl_xor_sync(0xffffffffu, p2, 2);
        p3 += __shfl_xor_sync(0xffffffffu, p3, 2);
        float w0 = __expf(p0), w1 = __expf(p1), w2 = __expf(p2), w3 = __expf(p3);
        denA += w0 + w2; denB += w1 + w3;
        numA.x = fmaf(w0, x0.x, fmaf(w2, x2.x, numA.x));
        numA.y = fmaf(w0, x0.y, fmaf(w2, x2.y, numA.y));
        numA.z = fmaf(w0, x0.z, fmaf(w2, x2.z, numA.z));
        numA.w = fmaf(w0, x0.w, fmaf(w2, x2.w, numA.w));
        numB.x = fmaf(w1, x1.x, fmaf(w3, x3.x, numB.x));
        numB.y = fmaf(w1, x1.y, fmaf(w3, x3.y, numB.y));
        numB.z = fmaf(w1, x1.z, fmaf(w3, x3.z, numB.z));
        numB.w = fmaf(w1, x1.w, fmaf(w3, x3.w, numB.w));
        e = en;
    }
    for (; e < end; e++) {
        int2 er = g_edge[e];
        float a0 = __int_as_float(er.y);
        float4 x0; xl1_load(er.x, c0, x0);
        float u0, u1, u2, u3;
        u0 = x0.x + xr.x + a0 * we.x; u0 = u0 > 0.f ? u0 : SLOPE * u0;
        u1 = x0.y + xr.y + a0 * we.y; u1 = u1 > 0.f ? u1 : SLOPE * u1;
        u2 = x0.z + xr.z + a0 * we.z; u2 = u2 > 0.f ? u2 : SLOPE * u2;
        u3 = x0.w + xr.w + a0 * we.w; u3 = u3 > 0.f ? u3 : SLOPE * u3;
        float p0 = u0 * at.x + u1 * at.y + u2 * at.z + u3 * at.w;
        p0 += __shfl_xor_sync(0xffffffffu, p0, 1);
        p0 += __shfl_xor_sync(0xffffffffu, p0, 2);
        float w0 = __expf(p0);
        denA += w0;
        numA.x = fmaf(w0, x0.x, numA.x); numA.y = fmaf(w0, x0.y, numA.y);
        numA.z = fmaf(w0, x0.z, numA.z); numA.w = fmaf(w0, x0.w, numA.w);
    }
    float inv = 1.f / (denA + denB);
    float4 o = {(numA.x + numB.x) * inv, (numA.y + numB.y) * inv,
                (numA.z + numB.z) * inv, (numA.w + numB.w) * inv};
    *(float4*)(g_out1 + (size_t)n * HID + c0) = o;
    atomicAdd(&ssum[c0 + 0], o.x); atomicAdd(&ssq[c0 + 0], o.x * o.x);
    atomicAdd(&ssum[c0 + 1], o.y); atomicAdd(&ssq[c0 + 1], o.y * o.y);
    atomicAdd(&ssum[c0 + 2], o.z); atomicAdd(&ssq[c0 + 2], o.z * o.z);
    atomicAdd(&ssum[c0 + 3], o.w); atomicAdd(&ssq[c0 + 3], o.w * o.w);
    __syncthreads();
    if (t < HID) { atomicAdd(&g_bnsum[t], ssum[t]); atomicAdd(&g_bnsq[t], ssq[t]); }
}

__global__ void k_agg2(const float* __restrict__ We, const float* __restrict__ att) {
    __shared__ float ssum[EMB], ssq[EMB];
    int t = threadIdx.x;
    if (t < EMB) { ssum[t] = 0.f; ssq[t] = 0.f; }
    __syncthreads();
    int n = (blockIdx.x * blockDim.x + t) >> 5;
    int lane = t & 31;
    int start = g_rowstart[n];
    int end = start + g_ideg[n] + 1;
    int c0 = lane * 2;
    float2 xr = *(const float2*)(g_xr2 + (size_t)n * EMB + c0);
    float2 we = *(const float2*)(We + c0);
    float2 at = *(const float2*)(att + c0);
    float2 numA = {0.f, 0.f}, numB = {0.f, 0.f};
    float denA = 0.f, denB = 0.f;
    int e = start;
    int2 r0, r1, r2, r3;
    if (e + 3 < end) {
        r0 = g_edge[e]; r1 = g_edge[e + 1]; r2 = g_edge[e + 2]; r3 = g_edge[e + 3];
    }
    while (e + 3 < end) {
        int s0 = r0.x, s1 = r1.x, s2 = r2.x, s3 = r3.x;
        float a0 = __int_as_float(r0.y), a1 = __int_as_float(r1.y);
        float a2 = __int_as_float(r2.y), a3 = __int_as_float(r3.y);
        float2 x0 = *(const float2*)(g_xl2 + (size_t)s0 * EMB + c0);
        float2 x1 = *(const float2*)(g_xl2 + (size_t)s1 * EMB + c0);
        float2 x2 = *(const float2*)(g_xl2 + (size_t)s2 * EMB + c0);
        float2 x3 = *(const float2*)(g_xl2 + (size_t)s3 * EMB + c0);
        int en = e + 4;
        if (en + 3 < end) {
            r0 = g_edge[en]; r1 = g_edge[en + 1]; r2 = g_edge[en + 2]; r3 = g_edge[en + 3];
        }
        float u0, u1;
        u0 = x0.x + xr.x + a0 * we.x; u0 = u0 > 0.f ? u0 : SLOPE * u0;
        u1 = x0.y + xr.y + a0 * we.y; u1 = u1 > 0.f ? u1 : SLOPE * u1;
        float p0 = u0 * at.x + u1 * at.y;
        u0 = x1.x + xr.x + a1 * we.x; u0 = u0 > 0.f ? u0 : SLOPE * u0;
        u1 = x1.y + xr.y + a1 * we.y; u1 = u1 > 0.f ? u1 : SLOPE * u1;
        float p1 = u0 * at.x + u1 * at.y;
        u0 = x2.x + xr.x + a2 * we.x; u0 = u0 > 0.f ? u0 : SLOPE * u0;
        u1 = x2.y + xr.y + a2 * we.y; u1 = u1 > 0.f ? u1 : SLOPE * u1;
        float p2 = u0 * at.x + u1 * at.y;
        u0 = x3.x + xr.x + a3 * we.x; u0 = u0 > 0.f ? u0 : SLOPE * u0;
        u1 = x3.y + xr.y + a3 * we.y; u1 = u1 > 0.f ? u1 : SLOPE * u1;
        float p3 = u0 * at.x + u1 * at.y;
#pragma unroll
        for (int off = 16; off > 0; off >>= 1) {
            p0 += __shfl_xor_sync(0xffffffffu, p0, off);
            p1 += __shfl_xor_sync(0xffffffffu, p1, off);
            p2 += __shfl_xor_sync(0xffffffffu, p2, off);
            p3 += __shfl_xor_sync(0xffffffffu, p3, off);
        }
        float w0 = __expf(p0), w1 = __expf(p1), w2 = __expf(p2), w3 = __expf(p3);
        denA += w0 + w2; denB += w1 + w3;
        numA.x = fmaf(w0, x0.x, fmaf(w2, x2.x, numA.x));
        numA.y = fmaf(w0, x0.y, fmaf(w2, x2.y, numA.y));
        numB.x = fmaf(w1, x1.x, fmaf(w3, x3.x, numB.x));
        numB.y = fmaf(w1, x1.y, fmaf(w3, x3.y, numB.y));
        e = en;
    }
    for (; e < end; e++) {
        int2 er = g_edge[e];
        float a0 = __int_as_float(er.y);
        float2 x0 = *(const float2*)(g_xl2 + (size_t)er.x * EMB + c0);
        float u0, u1;
        u0 = x0.x + xr.x + a0 * we.x; u0 = u0 > 0.f ? u0 : SLOPE * u0;
        u1 = x0.y + xr.y + a0 * we.y; u1 = u1 > 0.f ? u1 : SLOPE * u1;
        float p0 = u0 * at.x + u1 * at.y;
#pragma unroll
        for (int off = 16; off > 0; off >>= 1)
            p0 += __shfl_xor_sync(0xffffffffu, p0, off);
        float w0 = __expf(p0);
        denA += w0;
        numA.x = fmaf(w0, x0.x, numA.x); numA.y = fmaf(w0, x0.y, numA.y);
    }
    float inv = 1.f / (denA + denB);
    float2 o = {(numA.x + numB.x) * inv, (numA.y + numB.y) * inv};
    *(float2*)(g_out2 + (size_t)n * EMB + c0) = o;
    atomicAdd(&ssum[c0 + 0], o.x); atomicAdd(&ssq[c0 + 0], o.x * o.x);
    atomicAdd(&ssum[c0 + 1], o.y); atomicAdd(&ssq[c0 + 1], o.y * o.y);
    __syncthreads();
    if (t < EMB) { atomicAdd(&g_bnsum2[t], ssum[t]); atomicAdd(&g_bnsq2[t], ssq[t]); }
}

// BN2(inline) + relu + write node_emb + pooled sums
__global__ void k_bnapply2(const float* __restrict__ Yin, float* __restrict__ node_out,
                           const int* __restrict__ batch,
                           const float* __restrict__ gamma, const float* __restrict__ beta) {
    int i = blockIdx.x * blockDim.x + threadIdx.x;
    if (i >= NN * EMB) return;
    int c = i & (EMB - 1);
    int node = i >> 6;
    float mu = g_bnsum2[c] * (1.f / NN);
    float var = g_bnsq2[c] * (1.f / NN) - mu * mu;
    float sc = gamma[c] * rsqrtf(var + EPSV);
    float v = fmaf(Yin[i] - mu, sc, beta[c]);
    v = fmaxf(v, 0.f);
    node_out[i] = v;
    atomicAdd(&g_pool[batch[node] * EMB + c], v);
}

__global__ void k_poollogits(const float* __restrict__ Wc, const float* __restrict__ bc,
                             float* __restrict__ out) {
    int t = threadIdx.x;   // single block, 1024 threads
    for (int i = t; i < GG * EMB; i += blockDim.x) {
        int g = i >> 6;
        float dm = g_pool[i] / fmaxf(g_cnt[g], 1.f);
        g_dom[i] = dm;
        out[NCLS * GG + i] = dm;
    }
    __syncthreads();
    for (int p = t; p < GG * NCLS; p += blockDim.x) {
        int g = p / NCLS, c = p % NCLS;
        float acc = bc[c];
#pragma unroll 8
        for (int k = 0; k < EMB; k++)
            acc = fmaf(g_dom[g * EMB + k], Wc[k * NCLS + c], acc);
        out[p] = acc;
    }
}

// ---------------- host ----------------
extern "C" void kernel_launch(void* const* d_in, const int* in_sizes, int n_in,
                              void* d_out, int out_size) {
    const float* x     = (const float*)d_in[0];
    const int*   ei    = (const int*)d_in[1];
    const float* eattr = (const float*)d_in[2];
    const int*   batch = (const int*)d_in[3];
    const float* Wl1 = (const float*)d_in[4];  const float* bl1 = (const float*)d_in[5];
    const float* Wr1 = (const float*)d_in[6];  const float* br1 = (const float*)d_in[7];
    const float* We1 = (const float*)d_in[8];  const float* att1 = (const float*)d_in[9];
    // bias1 (d_in[10]) cancels exactly through BN1 -> skipped
    const float* Wl2 = (const float*)d_in[11]; const float* bl2 = (const float*)d_in[12];
    const float* Wr2 = (const float*)d_in[13]; const float* br2 = (const float*)d_in[14];
    const float* We2 = (const float*)d_in[15]; const float* att2 = (const float*)d_in[16];
    // bias2 (d_in[17]) cancels through BN2 -> skipped
    const float* gamma1 = (const float*)d_in[18]; const float* beta1 = (const float*)d_in[19];
    const float* gamma2 = (const float*)d_in[20]; const float* beta2 = (const float*)d_in[21];
    const float* Wc = (const float*)d_in[22]; const float* bc = (const float*)d_in[23];
    float* out = (float*)d_out;

    float *xr1, *out1, *xl2, *xr2, *out2;
    __half* xl1h;
    cudaGetSymbolAddress((void**)&xl1h, g_xl1h);
    cudaGetSymbolAddress((void**)&xr1, g_xr1);
    cudaGetSymbolAddress((void**)&out1, g_out1);
    cudaGetSymbolAddress((void**)&xl2, g_xl2);
    cudaGetSymbolAddress((void**)&xr2, g_xr2);
    cudaGetSymbolAddress((void**)&out2, g_out2);

    const int* src = ei;
    const int* dst = ei + EE;

    bool par = (g_side != nullptr);

    // ---- fork: gemm1 runs concurrent with CSR build ----
    if (par) {
        cudaEventRecord(g_evF, 0);
        cudaStreamWaitEvent(g_side, g_evF, 0);
    }
    k_gemm<FIN, false, true><<<dim3(391, 4), 256, 0, par ? g_side : 0>>>(
        x, Wl1, bl1, nullptr, xl1h, Wr1, br1, xr1, HID, 2, nullptr, nullptr);
    if (par) cudaEventRecord(g_evJ, g_side);

    // ---- CSR build (main stream, multi-block scan) ----
    k_zero<<<NB, 256>>>();
    k_hist<<<(EE + 255) / 256, 256>>>(dst, eattr);
    k_scanA<<<NB, 256>>>();
    k_scanB<<<1, 256>>>();
    k_scanC<<<NB, 256>>>(batch);
    k_scatterE<<<(EE + 255) / 256, 256>>>(src, dst, eattr);

    // ---- join ----
    if (par) cudaStreamWaitEvent(0, g_evJ, 0);

    // ---- layer 1 aggregation (+BN1 stats) ----
    k_agg1<<<6250, 256>>>(We1, att1);

    // ---- layer 2 (BN1+relu fused into GEMM X load) ----
    k_gemm<HID, true, false><<<dim3(391, 2), 256>>>(
        out1, Wl2, bl2, xl2, nullptr, Wr2, br2, xr2, EMB, 1, gamma1, beta1);
    k_agg2<<<6250, 256>>>(We2, att2);

    // ---- BN2 + pooling + classifier ----
    k_bnapply2<<<(NN * EMB + 255) / 256, 256>>>(out2, out + NCLS * GG + GG * EMB,
                                                batch, gamma2, beta2);
    k_poollogits<<<1, 1024>>>(Wc, bc, out);
}

// round 14
// speedup vs baseline: 1.1004x; 1.1004x over previous
#include <cuda_runtime.h>
#include <cuda_fp16.h>

#define NN 50000
#define EE 800000
#define ET 850000          // EE + NN self loops
#define GG 50
#define FIN 64
#define HID 128
#define EMB 64
#define H1 8
#define C1 16
#define NCLS 6
#define EPSV 1e-5f
#define SLOPE 0.2f
#define NB 196

// ---------------- scratch ----------------
__device__ int    g_ideg[NN], g_fill[NN], g_rowstart[NN];
__device__ int    g_psum[NB];
__device__ int2   g_edge[ET];          // {src, attr bits}
__device__ float  g_asum[NN];
__device__ __half g_xl1h[NN * HID];
__device__ float  g_xr1[NN * HID], g_out1[NN * HID];
__device__ float  g_xl2[NN * EMB], g_xr2[NN * EMB], g_out2[NN * EMB];
__device__ float  g_bnsum[HID], g_bnsq[HID];
__device__ float  g_bnsum2[EMB], g_bnsq2[EMB];
__device__ float  g_pool[GG * EMB], g_cnt[GG], g_dom[GG * EMB];

// ---------------- streams (static init; no device memory alloc) ----------------
static cudaStream_t g_side = nullptr;
static cudaEvent_t g_evF = nullptr, g_evJ = nullptr;
static struct SInit {
    SInit() {
        if (cudaStreamCreateWithFlags(&g_side, cudaStreamNonBlocking) != cudaSuccess) {
            g_side = nullptr; return;
        }
        if (cudaEventCreateWithFlags(&g_evF, cudaEventDisableTiming) != cudaSuccess ||
            cudaEventCreateWithFlags(&g_evJ, cudaEventDisableTiming) != cudaSuccess) {
            g_side = nullptr;
        }
    }
} s_init;

// ---------------- setup kernels ----------------
__global__ void k_zero() {
    int i = blockIdx.x * blockDim.x + threadIdx.x;
    if (i < NN) { g_ideg[i] = 0; g_fill[i] = 0; g_asum[i] = 0.f; }
    if (i < HID) { g_bnsum[i] = 0.f; g_bnsq[i] = 0.f; }
    if (i < EMB) { g_bnsum2[i] = 0.f; g_bnsq2[i] = 0.f; }
    if (i < GG * EMB) g_pool[i] = 0.f;
    if (i < GG) g_cnt[i] = 0.f;
}

__global__ void k_hist(const int* __restrict__ dst, const float* __restrict__ eattr) {
    int i = blockIdx.x * blockDim.x + threadIdx.x;
    if (i >= EE) return;
    int d = dst[i];
    atomicAdd(&g_ideg[d], 1);
    atomicAdd(&g_asum[d], eattr[i]);
}

__global__ void k_scanA() {
    __shared__ int s[256];
    int i = blockIdx.x * 256 + threadIdx.x;
    int v = (i < NN) ? g_ideg[i] + 1 : 0;
    s[threadIdx.x] = v; __syncthreads();
    for (int off = 128; off > 0; off >>= 1) {
        if (threadIdx.x < off) s[threadIdx.x] += s[threadIdx.x + off];
        __syncthreads();
    }
    if (threadIdx.x == 0) g_psum[blockIdx.x] = s[0];
}

// per-block scan with inline block-offset reduction (scanB folded in)
// + rowstart + self-loop record + batch counts
__global__ void k_scanC(const int* __restrict__ batch) {
    __shared__ int s[256];
    __shared__ int boff;
    int t = threadIdx.x;
    // block offset = sum of g_psum[j] for j < blockIdx.x
    int pv = (t < blockIdx.x && t < NB) ? g_psum[t] : 0;
    s[t] = pv; __syncthreads();
    for (int off = 128; off > 0; off >>= 1) {
        if (t < off) s[t] += s[t + off];
        __syncthreads();
    }
    if (t == 0) boff = s[0];
    __syncthreads();

    int i = blockIdx.x * 256 + t;
    int deg = (i < NN) ? g_ideg[i] : 0;
    int v = (i < NN) ? deg + 1 : 0;
    s[t] = v; __syncthreads();
    for (int off = 1; off < 256; off <<= 1) {
        int x = (t >= off) ? s[t - off] : 0;
        __syncthreads();
        s[t] += x;
        __syncthreads();
    }
    if (i < NN) {
        int rs = boff + s[t] - v;
        g_rowstart[i] = rs;
        float la = deg > 0 ? g_asum[i] / (float)deg : 0.f;
        g_edge[rs + deg] = make_int2(i, __float_as_int(la));   // self loop last
        atomicAdd(&g_cnt[batch[i]], 1.f);
    }
}

__global__ void k_scatterE(const int* __restrict__ src, const int* __restrict__ dst,
                           const float* __restrict__ eattr) {
    int e = blockIdx.x * blockDim.x + threadIdx.x;
    if (e >= EE) return;
    int d = dst[e];
    int pos = g_rowstart[d] + atomicAdd(&g_fill[d], 1);
    g_edge[pos] = make_int2(src[e], __float_as_int(eattr[e]));
}

// ---------------- tensor-core GEMM: mma.sync m16n8k16 fp16->fp32 -------------
#define LDSM_X4(r0, r1, r2, r3, addr) \
    asm volatile("ldmatrix.sync.aligned.m8n8.x4.shared.b16 {%0,%1,%2,%3}, [%4];" \
        : "=r"(r0), "=r"(r1), "=r"(r2), "=r"(r3) : "r"(addr))
#define LDSM_X4_T(r0, r1, r2, r3, addr) \
    asm volatile("ldmatrix.sync.aligned.m8n8.x4.trans.shared.b16 {%0,%1,%2,%3}, [%4];" \
        : "=r"(r0), "=r"(r1), "=r"(r2), "=r"(r3) : "r"(addr))
#define MMA16816(d, a0, a1, a2, a3, b0, b1) \
    asm volatile("mma.sync.aligned.m16n8k16.row.col.f32.f16.f16.f32 " \
        "{%0,%1,%2,%3}, {%4,%5,%6,%7}, {%8,%9}, {%0,%1,%2,%3};" \
        : "+f"((d)[0]), "+f"((d)[1]), "+f"((d)[2]), "+f"((d)[3]) \
        : "r"(a0), "r"(a1), "r"(a2), "r"(a3), "r"(b0), "r"(b1))

template<int KIN, bool BNF, bool HOUT>
__global__ void k_gemm(const float* __restrict__ X,
                       const float* __restrict__ W1, const float* __restrict__ b1,
                       float* __restrict__ Y1, __half* __restrict__ Y1h,
                       const float* __restrict__ W2, const float* __restrict__ b2,
                       float* __restrict__ Y2,
                       int kout, int tiles1,
                       const float* __restrict__ gamma, const float* __restrict__ beta) {
    __shared__ __half As[128][72];
    __shared__ __half Bs[64][72];
    __shared__ float sscale[128], sshift[128];
    int tid = threadIdx.x;
    if (BNF) {
        if (tid < KIN) {
            float mu = g_bnsum[tid] * (1.f / NN);
            float var = g_bnsq[tid] * (1.f / NN) - mu * mu;
            float sc = gamma[tid] * rsqrtf(var + EPSV);
            sscale[tid] = sc;
            sshift[tid] = beta[tid] - mu * sc;
        }
        __syncthreads();
    }
    int yt = blockIdx.y;
    bool first = yt < tiles1;
    const float* W; const float* bb; int colbase;
    if (first) { W = W1; bb = b1; colbase = yt * 64; }
    else       { W = W2; bb = b2; colbase = (yt - tiles1) * 64; }

    int warp = tid >> 5, lane = tid & 31;
    int wm = warp & 3, wn = warp >> 2;
    int r0 = blockIdx.x * 128;
    float acc[2][4][4] = {};

#pragma unroll
    for (int kc = 0; kc < KIN / 64; kc++) {
#pragma unroll
        for (int it = 0; it < 8; it++) {
            int idx = tid + it * 256;
            int row = idx >> 4, c4 = (idx & 15) * 4;
            int grow = r0 + row;
            float4 v = {0.f, 0.f, 0.f, 0.f};
            if (grow < NN)
                v = *(const float4*)(X + (size_t)grow * KIN + kc * 64 + c4);
            if (BNF) {
                int ka = kc * 64 + c4;
                v.x = fmaxf(fmaf(v.x, sscale[ka + 0], sshift[ka + 0]), 0.f);
                v.y = fmaxf(fmaf(v.y, sscale[ka + 1], sshift[ka + 1]), 0.f);
                v.z = fmaxf(fmaf(v.z, sscale[ka + 2], sshift[ka + 2]), 0.f);
                v.w = fmaxf(fmaf(v.w, sscale[ka + 3], sshift[ka + 3]), 0.f);
            }
            *(__half2*)&As[row][c4]     = __floats2half2_rn(v.x, v.y);
            *(__half2*)&As[row][c4 + 2] = __floats2half2_rn(v.z, v.w);
        }
#pragma unroll
        for (int it = 0; it < 4; it++) {
            int idx = tid + it * 256;
            int k = idx >> 4, c4 = (idx & 15) * 4;
            float4 v = *(const float4*)(W + (size_t)(kc * 64 + k) * kout + colbase + c4);
            *(__half2*)&Bs[k][c4]     = __floats2half2_rn(v.x, v.y);
            *(__half2*)&Bs[k][c4 + 2] = __floats2half2_rn(v.z, v.w);
        }
        __syncthreads();
#pragma unroll
        for (int ks = 0; ks < 4; ks++) {
            int k0 = ks * 16;
            unsigned a[2][4], b[2][4];
            int arow_base = wm * 32 + ((lane & 7) + 8 * ((lane >> 3) & 1));
            int acol = k0 + 8 * (lane >> 4);
#pragma unroll
            for (int mt = 0; mt < 2; mt++) {
                unsigned addr = (unsigned)__cvta_generic_to_shared(
                    &As[arow_base + mt * 16][acol]);
                LDSM_X4(a[mt][0], a[mt][1], a[mt][2], a[mt][3], addr);
            }
            int krow = k0 + (lane & 7) + 8 * ((lane >> 3) & 1);
#pragma unroll
            for (int np = 0; np < 2; np++) {
                int ncol = wn * 32 + np * 16 + 8 * (lane >> 4);
                unsigned addr = (unsigned)__cvta_generic_to_shared(&Bs[krow][ncol]);
                LDSM_X4_T(b[np][0], b[np][1], b[np][2], b[np][3], addr);
            }
#pragma unroll
            for (int mt = 0; mt < 2; mt++)
#pragma unroll
                for (int nt = 0; nt < 4; nt++) {
                    unsigned b0 = b[nt >> 1][(nt & 1) * 2 + 0];
                    unsigned b1 = b[nt >> 1][(nt & 1) * 2 + 1];
                    MMA16816(acc[mt][nt], a[mt][0], a[mt][1], a[mt][2], a[mt][3], b0, b1);
                }
        }
        __syncthreads();
    }

    int gID = lane >> 2, tig = lane & 3;
#pragma unroll
    for (int mt = 0; mt < 2; mt++)
#pragma unroll
        for (int nt = 0; nt < 4; nt++) {
            int col = colbase + wn * 32 + nt * 8 + tig * 2;
            float bias0 = bb[col], bias1 = bb[col + 1];
#pragma unroll
            for (int hrow = 0; hrow < 2; hrow++) {
                int row = r0 + wm * 32 + mt * 16 + gID + hrow * 8;
                if (row < NN) {
                    float o0 = acc[mt][nt][hrow * 2 + 0] + bias0;
                    float o1 = acc[mt][nt][hrow * 2 + 1] + bias1;
                    if (HOUT && first) {
                        *(__half2*)(Y1h + (size_t)row * kout + col) =
                            __floats2half2_rn(o0, o1);
                    } else {
                        float* Y = first ? Y1 : Y2;
                        float2 o = {o0, o1};
                        *(float2*)(Y + (size_t)row * kout + col) = o;
                    }
                }
            }
        }
}

// ---------------- fused GATv2 aggregation + BN stats: warp/node, 4-edge batch ----
__device__ __forceinline__ void xl1_load(int s, int c0, float4& f) {
    uint2 raw = *(const uint2*)(g_xl1h + (size_t)s * HID + c0);
    float2 f01 = __half22float2(*(__half2*)&raw.x);
    float2 f23 = __half22float2(*(__half2*)&raw.y);
    f.x = f01.x; f.y = f01.y; f.z = f23.x; f.w = f23.y;
}

__global__ void k_agg1(const float* __restrict__ We, const float* __restrict__ att) {
    __shared__ float ssum[HID], ssq[HID];
    int t = threadIdx.x;
    if (t < HID) { ssum[t] = 0.f; ssq[t] = 0.f; }
    __syncthreads();
    int n = (blockIdx.x * blockDim.x + t) >> 5;
    int lane = t & 31;
    int start = g_rowstart[n];
    int end = start + g_ideg[n] + 1;
    int c0 = lane * 4;
    float4 xr = *(const float4*)(g_xr1 + (size_t)n * HID + c0);
    float4 we = *(const float4*)(We + c0);
    int h = lane >> 2;
    float4 at = *(const float4*)(att + h * C1 + (lane & 3) * 4);
    float4 numA = {0.f, 0.f, 0.f, 0.f}, numB = {0.f, 0.f, 0.f, 0.f};
    float denA = 0.f, denB = 0.f;
    int e = start;
    for (; e + 3 < end; e += 4) {
        int2 e0 = g_edge[e], e1 = g_edge[e + 1], e2i = g_edge[e + 2], e3i = g_edge[e + 3];
        float a0 = __int_as_float(e0.y), a1 = __int_as_float(e1.y);
        float a2 = __int_as_float(e2i.y), a3 = __int_as_float(e3i.y);
        float4 x0, x1, x2, x3;
        xl1_load(e0.x, c0, x0);
        xl1_load(e1.x, c0, x1);
        xl1_load(e2i.x, c0, x2);
        xl1_load(e3i.x, c0, x3);
        float u0, u1, u2, u3;
        u0 = x0.x + xr.x + a0 * we.x; u0 = u0 > 0.f ? u0 : SLOPE * u0;
        u1 = x0.y + xr.y + a0 * we.y; u1 = u1 > 0.f ? u1 : SLOPE * u1;
        u2 = x0.z + xr.z + a0 * we.z; u2 = u2 > 0.f ? u2 : SLOPE * u2;
        u3 = x0.w + xr.w + a0 * we.w; u3 = u3 > 0.f ? u3 : SLOPE * u3;
        float p0 = u0 * at.x + u1 * at.y + u2 * at.z + u3 * at.w;
        u0 = x1.x + xr.x + a1 * we.x; u0 = u0 > 0.f ? u0 : SLOPE * u0;
        u1 = x1.y + xr.y + a1 * we.y; u1 = u1 > 0.f ? u1 : SLOPE * u1;
        u2 = x1.z + xr.z + a1 * we.z; u2 = u2 > 0.f ? u2 : SLOPE * u2;
        u3 = x1.w + xr.w + a1 * we.w; u3 = u3 > 0.f ? u3 : SLOPE * u3;
        float p1 = u0 * at.x + u1 * at.y + u2 * at.z + u3 * at.w;
        u0 = x2.x + xr.x + a2 * we.x; u0 = u0 > 0.f ? u0 : SLOPE * u0;
        u1 = x2.y + xr.y + a2 * we.y; u1 = u1 > 0.f ? u1 : SLOPE * u1;
        u2 = x2.z + xr.z + a2 * we.z; u2 = u2 > 0.f ? u2 : SLOPE * u2;
        u3 = x2.w + xr.w + a2 * we.w; u3 = u3 > 0.f ? u3 : SLOPE * u3;
        float p2 = u0 * at.x + u1 * at.y + u2 * at.z + u3 * at.w;
        u0 = x3.x + xr.x + a3 * we.x; u0 = u0 > 0.f ? u0 : SLOPE * u0;
        u1 = x3.y + xr.y + a3 * we.y; u1 = u1 > 0.f ? u1 : SLOPE * u1;
        u2 = x3.z + xr.z + a3 * we.z; u2 = u2 > 0.f ? u2 : SLOPE * u2;
        u3 = x3.w + xr.w + a3 * we.w; u3 = u3 > 0.f ? u3 : SLOPE * u3;
        float p3 = u0 * at.x + u1 * at.y + u2 * at.z + u3 * at.w;
        p0 += __shfl_xor_sync(0xffffffffu, p0, 1);
        p1 += __shfl_xor_sync(0xffffffffu, p1, 1);
        p2 += __shfl_xor_sync(0xffffffffu, p2, 1);
        p3 += __shfl_xor_sync(0xffffffffu, p3, 1);
        p0 += __shfl_xor_sync(0xffffffffu, p0, 2);
        p1 += __shfl_xor_sync(0xffffffffu, p1, 2);
        p2 += __shfl_xor_sync(0xffffffffu, p2, 2);
        p3 += __shfl_xor_sync(0xffffffffu, p3, 2);
        float w0 = __expf(p0), w1 = __expf(p1), w2 = __expf(p2), w3 = __expf(p3);
        denA += w0 + w2; denB += w1 + w3;
        numA.x = fmaf(w0, x0.x, fmaf(w2, x2.x, numA.x));
        numA.y = fmaf(w0, x0.y, fmaf(w2, x2.y, numA.y));
        numA.z = fmaf(w0, x0.z, fmaf(w2, x2.z, numA.z));
        numA.w = fmaf(w0, x0.w, fmaf(w2, x2.w, numA.w));
        numB.x = fmaf(w1, x1.x, fmaf(w3, x3.x, numB.x));
        numB.y = fmaf(w1, x1.y, fmaf(w3, x3.y, numB.y));
        numB.z = fmaf(w1, x1.z, fmaf(w3, x3.z, numB.z));
        numB.w = fmaf(w1, x1.w, fmaf(w3, x3.w, numB.w));
    }
    for (; e < end; e++) {
        int2 er = g_edge[e];
        float a0 = __int_as_float(er.y);
        float4 x0; xl1_load(er.x, c0, x0);
        float u0, u1, u2, u3;
        u0 = x0.x + xr.x + a0 * we.x; u0 = u0 > 0.f ? u0 : SLOPE * u0;
        u1 = x0.y + xr.y + a0 * we.y; u1 = u1 > 0.f ? u1 : SLOPE * u1;
        u2 = x0.z + xr.z + a0 * we.z; u2 = u2 > 0.f ? u2 : SLOPE * u2;
        u3 = x0.w + xr.w + a0 * we.w; u3 = u3 > 0.f ? u3 : SLOPE * u3;
        float p0 = u0 * at.x + u1 * at.y + u2 * at.z + u3 * at.w;
        p0 += __shfl_xor_sync(0xffffffffu, p0, 1);
        p0 += __shfl_xor_sync(0xffffffffu, p0, 2);
        float w0 = __expf(p0);
        denA += w0;
        numA.x = fmaf(w0, x0.x, numA.x); numA.y = fmaf(w0, x0.y, numA.y);
        numA.z = fmaf(w0, x0.z, numA.z); numA.w = fmaf(w0, x0.w, numA.w);
    }
    float inv = 1.f / (denA + denB);
    float4 o = {(numA.x + numB.x) * inv, (numA.y + numB.y) * inv,
                (numA.z + numB.z) * inv, (numA.w + numB.w) * inv};
    *(float4*)(g_out1 + (size_t)n * HID + c0) = o;
    atomicAdd(&ssum[c0 + 0], o.x); atomicAdd(&ssq[c0 + 0], o.x * o.x);
    atomicAdd(&ssum[c0 + 1], o.y); atomicAdd(&ssq[c0 + 1], o.y * o.y);
    atomicAdd(&ssum[c0 + 2], o.z); atomicAdd(&ssq[c0 + 2], o.z * o.z);
    atomicAdd(&ssum[c0 + 3], o.w); atomicAdd(&ssq[c0 + 3], o.w * o.w);
    __syncthreads();
    if (t < HID) { atomicAdd(&g_bnsum[t], ssum[t]); atomicAdd(&g_bnsq[t], ssq[t]); }
}

__global__ void k_agg2(const float* __restrict__ We, const float* __restrict__ att) {
    __shared__ float ssum[EMB], ssq[EMB];
    int t = threadIdx.x;
    if (t < EMB) { ssum[t] = 0.f; ssq[t] = 0.f; }
    __syncthreads();
    int n = (blockIdx.x * blockDim.x + t) >> 5;
    int lane = t & 31;
    int start = g_rowstart[n];
    int end = start + g_ideg[n] + 1;
    int c0 = lane * 2;
    float2 xr = *(const float2*)(g_xr2 + (size_t)n * EMB + c0);
    float2 we = *(const float2*)(We + c0);
    float2 at = *(const float2*)(att + c0);
    float2 numA = {0.f, 0.f}, numB = {0.f, 0.f};
    float denA = 0.f, denB = 0.f;
    int e = start;
    for (; e + 3 < end; e += 4) {
        int2 e0 = g_edge[e], e1 = g_edge[e + 1], e2i = g_edge[e + 2], e3i = g_edge[e + 3];
        float a0 = __int_as_float(e0.y), a1 = __int_as_float(e1.y);
        float a2 = __int_as_float(e2i.y), a3 = __int_as_float(e3i.y);
        float2 x0 = *(const float2*)(g_xl2 + (size_t)e0.x * EMB + c0);
        float2 x1 = *(const float2*)(g_xl2 + (size_t)e1.x * EMB + c0);
        float2 x2 = *(const float2*)(g_xl2 + (size_t)e2i.x * EMB + c0);
        float2 x3 = *(const float2*)(g_xl2 + (size_t)e3i.x * EMB + c0);
        float u0, u1;
        u0 = x0.x + xr.x + a0 * we.x; u0 = u0 > 0.f ? u0 : SLOPE * u0;
        u1 = x0.y + xr.y + a0 * we.y; u1 = u1 > 0.f ? u1 : SLOPE * u1;
        float p0 = u0 * at.x + u1 * at.y;
        u0 = x1.x + xr.x + a1 * we.x; u0 = u0 > 0.f ? u0 : SLOPE * u0;
        u1 = x1.y + xr.y + a1 * we.y; u1 = u1 > 0.f ? u1 : SLOPE * u1;
        float p1 = u0 * at.x + u1 * at.y;
        u0 = x2.x + xr.x + a2 * we.x; u0 = u0 > 0.f ? u0 : SLOPE * u0;
        u1 = x2.y + xr.y + a2 * we.y; u1 = u1 > 0.f ? u1 : SLOPE * u1;
        float p2 = u0 * at.x + u1 * at.y;
        u0 = x3.x + xr.x + a3 * we.x; u0 = u0 > 0.f ? u0 : SLOPE * u0;
        u1 = x3.y + xr.y + a3 * we.y; u1 = u1 > 0.f ? u1 : SLOPE * u1;
        float p3 = u0 * at.x + u1 * at.y;
#pragma unroll
        for (int off = 16; off > 0; off >>= 1) {
            p0 += __shfl_xor_sync(0xffffffffu, p0, off);
            p1 += __shfl_xor_sync(0xffffffffu, p1, off);
            p2 += __shfl_xor_sync(0xffffffffu, p2, off);
            p3 += __shfl_xor_sync(0xffffffffu, p3, off);
        }
        float w0 = __expf(p0), w1 = __expf(p1), w2 = __expf(p2), w3 = __expf(p3);
        denA += w0 + w2; denB += w1 + w3;
        numA.x = fmaf(w0, x0.x, fmaf(w2, x2.x, numA.x));
        numA.y = fmaf(w0, x0.y, fmaf(w2, x2.y, numA.y));
        numB.x = fmaf(w1, x1.x, fmaf(w3, x3.x, numB.x));
        numB.y = fmaf(w1, x1.y, fmaf(w3, x3.y, numB.y));
    }
    for (; e < end; e++) {
        int2 er = g_edge[e];
        float a0 = __int_as_float(er.y);
        float2 x0 = *(const float2*)(g_xl2 + (size_t)er.x * EMB + c0);
        float u0, u1;
        u0 = x0.x + xr.x + a0 * we.x; u0 = u0 > 0.f ? u0 : SLOPE * u0;
        u1 = x0.y + xr.y + a0 * we.y; u1 = u1 > 0.f ? u1 : SLOPE * u1;
        float p0 = u0 * at.x + u1 * at.y;
#pragma unroll
        for (int off = 16; off > 0; off >>= 1)
            p0 += __shfl_xor_sync(0xffffffffu, p0, off);
        float w0 = __expf(p0);
        denA += w0;
        numA.x = fmaf(w0, x0.x, numA.x); numA.y = fmaf(w0, x0.y, numA.y);
    }
    float inv = 1.f / (denA + denB);
    float2 o = {(numA.x + numB.x) * inv, (numA.y + numB.y) * inv};
    *(float2*)(g_out2 + (size_t)n * EMB + c0) = o;
    atomicAdd(&ssum[c0 + 0], o.x); atomicAdd(&ssq[c0 + 0], o.x * o.x);
    atomicAdd(&ssum[c0 + 1], o.y); atomicAdd(&ssq[c0 + 1], o.y * o.y);
    __syncthreads();
    if (t < EMB) { atomicAdd(&g_bnsum2[t], ssum[t]); atomicAdd(&g_bnsq2[t], ssq[t]); }
}

// BN2(inline) + relu + node_emb + smem-staged pool sums (batch is sorted)
__global__ void k_bnapply2(const float* __restrict__ Yin, float* __restrict__ node_out,
                           const int* __restrict__ batch,
                           const float* __restrict__ gamma, const float* __restrict__ beta) {
    __shared__ float sp[256];
    __shared__ int sg[4];
    int t = threadIdx.x;
    int i = blockIdx.x * 256 + t;   // grid covers NN*EMB exactly (12500 blocks)
    int c = i & (EMB - 1);
    int node = i >> 6;
    float mu = g_bnsum2[c] * (1.f / NN);
    float var = g_bnsq2[c] * (1.f / NN) - mu * mu;
    float sc = gamma[c] * rsqrtf(var + EPSV);
    float v = fmaf(Yin[i] - mu, sc, beta[c]);
    v = fmaxf(v, 0.f);
    node_out[i] = v;
    int g = batch[node];
    sg[t >> 6] = g;       // benign same-value race per node slot
    sp[t] = v;
    __syncthreads();
    if (sg[0] == sg[3]) { // all 4 nodes in one graph (common: batch sorted)
        if (t < EMB) {
            float sum = sp[t] + sp[t + 64] + sp[t + 128] + sp[t + 192];
            atomicAdd(&g_pool[sg[0] * EMB + t], sum);
        }
    } else {
        atomicAdd(&g_pool[g * EMB + c], v);
    }
}

__global__ void k_poollogits(const float* __restrict__ Wc, const float* __restrict__ bc,
                             float* __restrict__ out) {
    int t = threadIdx.x;   // single block, 1024 threads
    for (int i = t; i < GG * EMB; i += blockDim.x) {
        int g = i >> 6;
        float dm = g_pool[i] / fmaxf(g_cnt[g], 1.f);
        g_dom[i] = dm;
        out[NCLS * GG + i] = dm;
    }
    __syncthreads();
    for (int p = t; p < GG * NCLS; p += blockDim.x) {
        int g = p / NCLS, c = p % NCLS;
        float acc = bc[c];
#pragma unroll 8
        for (int k = 0; k < EMB; k++)
            acc = fmaf(g_dom[g * EMB + k], Wc[k * NCLS + c], acc);
        out[p] = acc;
    }
}

// ---------------- host ----------------
extern "C" void kernel_launch(void* const* d_in, const int* in_sizes, int n_in,
                              void* d_out, int out_size) {
    const float* x     = (const float*)d_in[0];
    const int*   ei    = (const int*)d_in[1];
    const float* eattr = (const float*)d_in[2];
    const int*   batch = (const int*)d_in[3];
    const float* Wl1 = (const float*)d_in[4];  const float* bl1 = (const float*)d_in[5];
    const float* Wr1 = (const float*)d_in[6];  const float* br1 = (const float*)d_in[7];
    const float* We1 = (const float*)d_in[8];  const float* att1 = (const float*)d_in[9];
    // bias1 (d_in[10]) cancels exactly through BN1 -> skipped
    const float* Wl2 = (const float*)d_in[11]; const float* bl2 = (const float*)d_in[12];
    const float* Wr2 = (const float*)d_in[13]; const float* br2 = (const float*)d_in[14];
    const float* We2 = (const float*)d_in[15]; const float* att2 = (const float*)d_in[16];
    // bias2 (d_in[17]) cancels through BN2 -> skipped
    const float* gamma1 = (const float*)d_in[18]; const float* beta1 = (const float*)d_in[19];
    const float* gamma2 = (const float*)d_in[20]; const float* beta2 = (const float*)d_in[21];
    const float* Wc = (const float*)d_in[22]; const float* bc = (const float*)d_in[23];
    float* out = (float*)d_out;

    float *xr1, *out1, *xl2, *xr2, *out2;
    __half* xl1h;
    cudaGetSymbolAddress((void**)&xl1h, g_xl1h);
    cudaGetSymbolAddress((void**)&xr1, g_xr1);
    cudaGetSymbolAddress((void**)&out1, g_out1);
    cudaGetSymbolAddress((void**)&xl2, g_xl2);
    cudaGetSymbolAddress((void**)&xr2, g_xr2);
    cudaGetSymbolAddress((void**)&out2, g_out2);

    const int* src = ei;
    const int* dst = ei + EE;

    bool par = (g_side != nullptr);

    // ---- fork: gemm1 runs concurrent with CSR build ----
    if (par) {
        cudaEventRecord(g_evF, 0);
        cudaStreamWaitEvent(g_side, g_evF, 0);
    }
    k_gemm<FIN, false, true><<<dim3(391, 4), 256, 0, par ? g_side : 0>>>(
        x, Wl1, bl1, nullptr, xl1h, Wr1, br1, xr1, HID, 2, nullptr, nullptr);
    if (par) cudaEventRecord(g_evJ, g_side);

    // ---- CSR build (main stream) ----
    k_zero<<<NB, 256>>>();
    k_hist<<<(EE + 255) / 256, 256>>>(dst, eattr);
    k_scanA<<<NB, 256>>>();
    k_scanC<<<NB, 256>>>(batch);
    k_scatterE<<<(EE + 255) / 256, 256>>>(src, dst, eattr);

    // ---- join ----
    if (par) cudaStreamWaitEvent(0, g_evJ, 0);

    // ---- layer 1 aggregation (+BN1 stats) ----
    k_agg1<<<6250, 256>>>(We1, att1);

    // ---- layer 2 (BN1+relu fused into GEMM X load) ----
    k_gemm<HID, true, false><<<dim3(391, 2), 256>>>(
        out1, Wl2, bl2, xl2, nullptr, Wr2, br2, xr2, EMB, 1, gamma1, beta1);
    k_agg2<<<6250, 256>>>(We2, att2);

    // ---- BN2 + pooling + classifier ----
    k_bnapply2<<<(NN * EMB) / 256, 256>>>(out2, out + NCLS * GG + GG * EMB,
                                          batch, gamma2, beta2);
    k_poollogits<<<1, 1024>>>(Wc, bc, out);
}

// round 15
// speedup vs baseline: 1.1505x; 1.0455x over previous
#include <cuda_runtime.h>
#include <cuda_fp16.h>

#define NN 50000
#define EE 800000
#define ET 850000          // EE + NN self loops
#define GG 50
#define FIN 64
#define HID 128
#define EMB 64
#define H1 8
#define C1 16
#define NCLS 6
#define EPSV 1e-5f
#define SLOPE 0.2f
#define NB 196

// ---------------- scratch ----------------
__device__ unsigned long long g_histpack[NN];   // hi: eattr sum (2^20 fixed), lo: deg
__device__ int    g_ideg[NN], g_rowstart[NN];
__device__ int    g_psum[NB], g_flag[NB];
__device__ int    g_slot[EE];
__device__ int2   g_edge[ET];          // {src, attr bits}
__device__ __half g_xl1h[NN * HID];
__device__ float  g_xr1[NN * HID], g_out1[NN * HID];
__device__ float  g_xl2[NN * EMB], g_xr2[NN * EMB], g_out2[NN * EMB];
__device__ float  g_bnsum[HID], g_bnsq[HID];
__device__ float  g_bnsum2[EMB], g_bnsq2[EMB];
__device__ float  g_pool[GG * EMB], g_cnt[GG], g_dom[GG * EMB];

// ---------------- streams (static init; no device memory alloc) ----------------
static cudaStream_t g_side = nullptr;
static cudaEvent_t g_evF = nullptr, g_evJ = nullptr;
static struct SInit {
    SInit() {
        if (cudaStreamCreateWithFlags(&g_side, cudaStreamNonBlocking) != cudaSuccess) {
            g_side = nullptr; return;
        }
        if (cudaEventCreateWithFlags(&g_evF, cudaEventDisableTiming) != cudaSuccess ||
            cudaEventCreateWithFlags(&g_evJ, cudaEventDisableTiming) != cudaSuccess) {
            g_side = nullptr;
        }
    }
} s_init;

// ---------------- setup kernels ----------------
__global__ void k_zero() {
    int i = blockIdx.x * blockDim.x + threadIdx.x;
    if (i < NN) g_histpack[i] = 0ull;
    if (i < HID) { g_bnsum[i] = 0.f; g_bnsq[i] = 0.f; }
    if (i < EMB) { g_bnsum2[i] = 0.f; g_bnsq2[i] = 0.f; }
    if (i < GG * EMB) g_pool[i] = 0.f;
    if (i < GG) g_cnt[i] = 0.f;
    if (i < NB) g_flag[i] = 0;
}

// one packed u64 atomic: hi += eattr*2^20, lo += 1; old lo = CSR slot
__global__ void k_hist(const int* __restrict__ dst, const float* __restrict__ eattr) {
    int e = blockIdx.x * blockDim.x + threadIdx.x;
    if (e >= EE) return;
    int d = dst[e];
    unsigned long long pk =
        ((unsigned long long)(unsigned)__float2int_rn(eattr[e] * 1048576.f) << 32) | 1ull;
    unsigned long long old = atomicAdd(&g_histpack[d], pk);
    g_slot[e] = (int)(old & 0xffffffffu);
}

// single-pass scan with decoupled lookback (all 196 blocks are wave-1 resident)
// + rowstart + ideg + self-loop record + batch counts
__global__ void k_scanAC(const int* __restrict__ batch) {
    __shared__ int s[256];
    __shared__ int spre[256];
    int t = threadIdx.x;
    int i = blockIdx.x * 256 + t;
    unsigned long long pk = (i < NN) ? g_histpack[i] : 0ull;
    int deg = (int)(pk & 0xffffffffu);
    int v = (i < NN) ? deg + 1 : 0;
    s[t] = v; __syncthreads();
    for (int off = 1; off < 256; off <<= 1) {
        int x = (t >= off) ? s[t - off] : 0;
        __syncthreads();
        s[t] += x;
        __syncthreads();
    }
    int incl = s[t];
    if (t == 0) {
        g_psum[blockIdx.x] = s[255];
        __threadfence();
        atomicExch(&g_flag[blockIdx.x], 1);
    }
    int pv = 0;
    if (t < blockIdx.x) {
        while (atomicAdd(&g_flag[t], 0) == 0) {}
        pv = g_psum[t];
    }
    spre[t] = pv; __syncthreads();
    for (int off = 128; off > 0; off >>= 1) {
        if (t < off) spre[t] += spre[t + off];
        __syncthreads();
    }
    int bo = spre[0];
    if (i < NN) {
        int rs = bo + incl - v;
        g_rowstart[i] = rs;
        g_ideg[i] = deg;
        float asum = (float)(pk >> 32) * (1.f / 1048576.f);
        float la = deg > 0 ? asum / (float)deg : 0.f;
        g_edge[rs + deg] = make_int2(i, __float_as_int(la));   // self loop last
        atomicAdd(&g_cnt[batch[i]], 1.f);
    }
}

// atomic-free scatter using slots recorded by k_hist
__global__ void k_scatterE(const int* __restrict__ src, const int* __restrict__ dst,
                           const float* __restrict__ eattr) {
    int e = blockIdx.x * blockDim.x + threadIdx.x;
    if (e >= EE) return;
    int d = dst[e];
    g_edge[g_rowstart[d] + g_slot[e]] = make_int2(src[e], __float_as_int(eattr[e]));
}

// ---------------- tensor-core GEMM: mma.sync m16n8k16 fp16->fp32 -------------
#define LDSM_X4(r0, r1, r2, r3, addr) \
    asm volatile("ldmatrix.sync.aligned.m8n8.x4.shared.b16 {%0,%1,%2,%3}, [%4];" \
        : "=r"(r0), "=r"(r1), "=r"(r2), "=r"(r3) : "r"(addr))
#define LDSM_X4_T(r0, r1, r2, r3, addr) \
    asm volatile("ldmatrix.sync.aligned.m8n8.x4.trans.shared.b16 {%0,%1,%2,%3}, [%4];" \
        : "=r"(r0), "=r"(r1), "=r"(r2), "=r"(r3) : "r"(addr))
#define MMA16816(d, a0, a1, a2, a3, b0, b1) \
    asm volatile("mma.sync.aligned.m16n8k16.row.col.f32.f16.f16.f32 " \
        "{%0,%1,%2,%3}, {%4,%5,%6,%7}, {%8,%9}, {%0,%1,%2,%3};" \
        : "+f"((d)[0]), "+f"((d)[1]), "+f"((d)[2]), "+f"((d)[3]) \
        : "r"(a0), "r"(a1), "r"(a2), "r"(a3), "r"(b0), "r"(b1))

template<int KIN, bool BNF, bool HOUT>
__global__ void k_gemm(const float* __restrict__ X,
                       const float* __restrict__ W1, const float* __restrict__ b1,
                       float* __restrict__ Y1, __half* __restrict__ Y1h,
                       const float* __restrict__ W2, const float* __restrict__ b2,
                       float* __restrict__ Y2,
                       int kout, int tiles1,
                       const float* __restrict__ gamma, const float* __restrict__ beta) {
    __shared__ __half As[128][72];
    __shared__ __half Bs[64][72];
    __shared__ float sscale[128], sshift[128];
    int tid = threadIdx.x;
    if (BNF) {
        if (tid < KIN) {
            float mu = g_bnsum[tid] * (1.f / NN);
            float var = g_bnsq[tid] * (1.f / NN) - mu * mu;
            float sc = gamma[tid] * rsqrtf(var + EPSV);
            sscale[tid] = sc;
            sshift[tid] = beta[tid] - mu * sc;
        }
        __syncthreads();
    }
    int yt = blockIdx.y;
    bool first = yt < tiles1;
    const float* W; const float* bb; int colbase;
    if (first) { W = W1; bb = b1; colbase = yt * 64; }
    else       { W = W2; bb = b2; colbase = (yt - tiles1) * 64; }

    int warp = tid >> 5, lane = tid & 31;
    int wm = warp & 3, wn = warp >> 2;
    int r0 = blockIdx.x * 128;
    float acc[2][4][4] = {};

#pragma unroll
    for (int kc = 0; kc < KIN / 64; kc++) {
#pragma unroll
        for (int it = 0; it < 8; it++) {
            int idx = tid + it * 256;
            int row = idx >> 4, c4 = (idx & 15) * 4;
            int grow = r0 + row;
            float4 v = {0.f, 0.f, 0.f, 0.f};
            if (grow < NN)
                v = *(const float4*)(X + (size_t)grow * KIN + kc * 64 + c4);
            if (BNF) {
                int ka = kc * 64 + c4;
                v.x = fmaxf(fmaf(v.x, sscale[ka + 0], sshift[ka + 0]), 0.f);
                v.y = fmaxf(fmaf(v.y, sscale[ka + 1], sshift[ka + 1]), 0.f);
                v.z = fmaxf(fmaf(v.z, sscale[ka + 2], sshift[ka + 2]), 0.f);
                v.w = fmaxf(fmaf(v.w, sscale[ka + 3], sshift[ka + 3]), 0.f);
            }
            *(__half2*)&As[row][c4]     = __floats2half2_rn(v.x, v.y);
            *(__half2*)&As[row][c4 + 2] = __floats2half2_rn(v.z, v.w);
        }
#pragma unroll
        for (int it = 0; it < 4; it++) {
            int idx = tid + it * 256;
            int k = idx >> 4, c4 = (idx & 15) * 4;
            float4 v = *(const float4*)(W + (size_t)(kc * 64 + k) * kout + colbase + c4);
            *(__half2*)&Bs[k][c4]     = __floats2half2_rn(v.x, v.y);
            *(__half2*)&Bs[k][c4 + 2] = __floats2half2_rn(v.z, v.w);
        }
        __syncthreads();
#pragma unroll
        for (int ks = 0; ks < 4; ks++) {
            int k0 = ks * 16;
            unsigned a[2][4], b[2][4];
            int arow_base = wm * 32 + ((lane & 7) + 8 * ((lane >> 3) & 1));
            int acol = k0 + 8 * (lane >> 4);
#pragma unroll
            for (int mt = 0; mt < 2; mt++) {
                unsigned addr = (unsigned)__cvta_generic_to_shared(
                    &As[arow_base + mt * 16][acol]);
                LDSM_X4(a[mt][0], a[mt][1], a[mt][2], a[mt][3], addr);
            }
            int krow = k0 + (lane & 7) + 8 * ((lane >> 3) & 1);
#pragma unroll
            for (int np = 0; np < 2; np++) {
                int ncol = wn * 32 + np * 16 + 8 * (lane >> 4);
                unsigned addr = (unsigned)__cvta_generic_to_shared(&Bs[krow][ncol]);
                LDSM_X4_T(b[np][0], b[np][1], b[np][2], b[np][3], addr);
            }
#pragma unroll
            for (int mt = 0; mt < 2; mt++)
#pragma unroll
                for (int nt = 0; nt < 4; nt++) {
                    unsigned b0 = b[nt >> 1][(nt & 1) * 2 + 0];
                    unsigned b1 = b[nt >> 1][(nt & 1) * 2 + 1];
                    MMA16816(acc[mt][nt], a[mt][0], a[mt][1], a[mt][2], a[mt][3], b0, b1);
                }
        }
        __syncthreads();
    }

    int gID = lane >> 2, tig = lane & 3;
#pragma unroll
    for (int mt = 0; mt < 2; mt++)
#pragma unroll
        for (int nt = 0; nt < 4; nt++) {
            int col = colbase + wn * 32 + nt * 8 + tig * 2;
            float bias0 = bb[col], bias1 = bb[col + 1];
#pragma unroll
            for (int hrow = 0; hrow < 2; hrow++) {
                int row = r0 + wm * 32 + mt * 16 + gID + hrow * 8;
                if (row < NN) {
                    float o0 = acc[mt][nt][hrow * 2 + 0] + bias0;
                    float o1 = acc[mt][nt][hrow * 2 + 1] + bias1;
                    if (HOUT && first) {
                        *(__half2*)(Y1h + (size_t)row * kout + col) =
                            __floats2half2_rn(o0, o1);
                    } else {
                        float* Y = first ? Y1 : Y2;
                        float2 o = {o0, o1};
                        *(float2*)(Y + (size_t)row * kout + col) = o;
                    }
                }
            }
        }
}

// ---------------- fused GATv2 aggregation + BN stats: warp/node, 4-edge batch ----
__device__ __forceinline__ void xl1_load(int s, int c0, float4& f) {
    uint2 raw = *(const uint2*)(g_xl1h + (size_t)s * HID + c0);
    float2 f01 = __half22float2(*(__half2*)&raw.x);
    float2 f23 = __half22float2(*(__half2*)&raw.y);
    f.x = f01.x; f.y = f01.y; f.z = f23.x; f.w = f23.y;
}

__global__ void k_agg1(const float* __restrict__ We, const float* __restrict__ att) {
    __shared__ float ssum[HID], ssq[HID];
    int t = threadIdx.x;
    if (t < HID) { ssum[t] = 0.f; ssq[t] = 0.f; }
    __syncthreads();
    int n = (blockIdx.x * blockDim.x + t) >> 5;
    int lane = t & 31;
    int start = g_rowstart[n];
    int end = start + g_ideg[n] + 1;
    int c0 = lane * 4;
    float4 xr = *(const float4*)(g_xr1 + (size_t)n * HID + c0);
    float4 we = *(const float4*)(We + c0);
    int h = lane >> 2;
    float4 at = *(const float4*)(att + h * C1 + (lane & 3) * 4);
    float4 numA = {0.f, 0.f, 0.f, 0.f}, numB = {0.f, 0.f, 0.f, 0.f};
    float denA = 0.f, denB = 0.f;
    int e = start;
    for (; e + 3 < end; e += 4) {
        int2 e0 = g_edge[e], e1 = g_edge[e + 1], e2i = g_edge[e + 2], e3i = g_edge[e + 3];
        float a0 = __int_as_float(e0.y), a1 = __int_as_float(e1.y);
        float a2 = __int_as_float(e2i.y), a3 = __int_as_float(e3i.y);
        float4 x0, x1, x2, x3;
        xl1_load(e0.x, c0, x0);
        xl1_load(e1.x, c0, x1);
        xl1_load(e2i.x, c0, x2);
        xl1_load(e3i.x, c0, x3);
        float u0, u1, u2, u3;
        u0 = x0.x + xr.x + a0 * we.x; u0 = u0 > 0.f ? u0 : SLOPE * u0;
        u1 = x0.y + xr.y + a0 * we.y; u1 = u1 > 0.f ? u1 : SLOPE * u1;
        u2 = x0.z + xr.z + a0 * we.z; u2 = u2 > 0.f ? u2 : SLOPE * u2;
        u3 = x0.w + xr.w + a0 * we.w; u3 = u3 > 0.f ? u3 : SLOPE * u3;
        float p0 = u0 * at.x + u1 * at.y + u2 * at.z + u3 * at.w;
        u0 = x1.x + xr.x + a1 * we.x; u0 = u0 > 0.f ? u0 : SLOPE * u0;
        u1 = x1.y + xr.y + a1 * we.y; u1 = u1 > 0.f ? u1 : SLOPE * u1;
        u2 = x1.z + xr.z + a1 * we.z; u2 = u2 > 0.f ? u2 : SLOPE * u2;
        u3 = x1.w + xr.w + a1 * we.w; u3 = u3 > 0.f ? u3 : SLOPE * u3;
        float p1 = u0 * at.x + u1 * at.y + u2 * at.z + u3 * at.w;
        u0 = x2.x + xr.x + a2 * we.x; u0 = u0 > 0.f ? u0 : SLOPE * u0;
        u1 = x2.y + xr.y + a2 * we.y; u1 = u1 > 0.f ? u1 : SLOPE * u1;
        u2 = x2.z + xr.z + a2 * we.z; u2 = u2 > 0.f ? u2 : SLOPE * u2;
        u3 = x2.w + xr.w + a2 * we.w; u3 = u3 > 0.f ? u3 : SLOPE * u3;
        float p2 = u0 * at.x + u1 * at.y + u2 * at.z + u3 * at.w;
        u0 = x3.x + xr.x + a3 * we.x; u0 = u0 > 0.f ? u0 : SLOPE * u0;
        u1 = x3.y + xr.y + a3 * we.y; u1 = u1 > 0.f ? u1 : SLOPE * u1;
        u2 = x3.z + xr.z + a3 * we.z; u2 = u2 > 0.f ? u2 : SLOPE * u2;
        u3 = x3.w + xr.w + a3 * we.w; u3 = u3 > 0.f ? u3 : SLOPE * u3;
        float p3 = u0 * at.x + u1 * at.y + u2 * at.z + u3 * at.w;
        p0 += __shfl_xor_sync(0xffffffffu, p0, 1);
        p1 += __shfl_xor_sync(0xffffffffu, p1, 1);
        p2 += __shfl_xor_sync(0xffffffffu, p2, 1);
        p3 += __shfl_xor_sync(0xffffffffu, p3, 1);
        p0 += __shfl_xor_sync(0xffffffffu, p0, 2);
        p1 += __shfl_xor_sync(0xffffffffu, p1, 2);
        p2 += __shfl_xor_sync(0xffffffffu, p2, 2);
        p3 += __shfl_xor_sync(0xffffffffu, p3, 2);
        float w0 = __expf(p0), w1 = __expf(p1), w2 = __expf(p2), w3 = __expf(p3);
        denA += w0 + w2; denB += w1 + w3;
        numA.x = fmaf(w0, x0.x, fmaf(w2, x2.x, numA.x));
        numA.y = fmaf(w0, x0.y, fmaf(w2, x2.y, numA.y));
        numA.z = fmaf(w0, x0.z, fmaf(w2, x2.z, numA.z));
        numA.w = fmaf(w0, x0.w, fmaf(w2, x2.w, numA.w));
        numB.x = fmaf(w1, x1.x, fmaf(w3, x3.x, numB.x));
        numB.y = fmaf(w1, x1.y, fmaf(w3, x3.y, numB.y));
        numB.z = fmaf(w1, x1.z, fmaf(w3, x3.z, numB.z));
        numB.w = fmaf(w1, x1.w, fmaf(w3, x3.w, numB.w));
    }
    for (; e < end; e++) {
        int2 er = g_edge[e];
        float a0 = __int_as_float(er.y);
        float4 x0; xl1_load(er.x, c0, x0);
        float u0, u1, u2, u3;
        u0 = x0.x + xr.x + a0 * we.x; u0 = u0 > 0.f ? u0 : SLOPE * u0;
        u1 = x0.y + xr.y + a0 * we.y; u1 = u1 > 0.f ? u1 : SLOPE * u1;
        u2 = x0.z + xr.z + a0 * we.z; u2 = u2 > 0.f ? u2 : SLOPE * u2;
        u3 = x0.w + xr.w + a0 * we.w; u3 = u3 > 0.f ? u3 : SLOPE * u3;
        float p0 = u0 * at.x + u1 * at.y + u2 * at.z + u3 * at.w;
        p0 += __shfl_xor_sync(0xffffffffu, p0, 1);
        p0 += __shfl_xor_sync(0xffffffffu, p0, 2);
        float w0 = __expf(p0);
        denA += w0;
        numA.x = fmaf(w0, x0.x, numA.x); numA.y = fmaf(w0, x0.y, numA.y);
        numA.z = fmaf(w0, x0.z, numA.z); numA.w = fmaf(w0, x0.w, numA.w);
    }
    float inv = 1.f / (denA + denB);
    float4 o = {(numA.x + numB.x) * inv, (numA.y + numB.y) * inv,
                (numA.z + numB.z) * inv, (numA.w + numB.w) * inv};
    *(float4*)(g_out1 + (size_t)n * HID + c0) = o;
    atomicAdd(&ssum[c0 + 0], o.x); atomicAdd(&ssq[c0 + 0], o.x * o.x);
    atomicAdd(&ssum[c0 + 1], o.y); atomicAdd(&ssq[c0 + 1], o.y * o.y);
    atomicAdd(&ssum[c0 + 2], o.z); atomicAdd(&ssq[c0 + 2], o.z * o.z);
    atomicAdd(&ssum[c0 + 3], o.w); atomicAdd(&ssq[c0 + 3], o.w * o.w);
    __syncthreads();
    if (t < HID) { atomicAdd(&g_bnsum[t], ssum[t]); atomicAdd(&g_bnsq[t], ssq[t]); }
}

__global__ void k_agg2(const float* __restrict__ We, const float* __restrict__ att) {
    __shared__ float ssum[EMB], ssq[EMB];
    int t = threadIdx.x;
    if (t < EMB) { ssum[t] = 0.f; ssq[t] = 0.f; }
    __syncthreads();
    int n = (blockIdx.x * blockDim.x + t) >> 5;
    int lane = t & 31;
    int start = g_rowstart[n];
    int end = start + g_ideg[n] + 1;
    int c0 = lane * 2;
    float2 xr = *(const float2*)(g_xr2 + (size_t)n * EMB + c0);
    float2 we = *(const float2*)(We + c0);
    float2 at = *(const float2*)(att + c0);
    float2 numA = {0.f, 0.f}, numB = {0.f, 0.f};
    float denA = 0.f, denB = 0.f;
    int e = start;
    for (; e + 3 < end; e += 4) {
        int2 e0 = g_edge[e], e1 = g_edge[e + 1], e2i = g_edge[e + 2], e3i = g_edge[e + 3];
        float a0 = __int_as_float(e0.y), a1 = __int_as_float(e1.y);
        float a2 = __int_as_float(e2i.y), a3 = __int_as_float(e3i.y);
        float2 x0 = *(const float2*)(g_xl2 + (size_t)e0.x * EMB + c0);
        float2 x1 = *(const float2*)(g_xl2 + (size_t)e1.x * EMB + c0);
        float2 x2 = *(const float2*)(g_xl2 + (size_t)e2i.x * EMB + c0);
        float2 x3 = *(const float2*)(g_xl2 + (size_t)e3i.x * EMB + c0);
        float u0, u1;
        u0 = x0.x + xr.x + a0 * we.x; u0 = u0 > 0.f ? u0 : SLOPE * u0;
        u1 = x0.y + xr.y + a0 * we.y; u1 = u1 > 0.f ? u1 : SLOPE * u1;
        float p0 = u0 * at.x + u1 * at.y;
        u0 = x1.x + xr.x + a1 * we.x; u0 = u0 > 0.f ? u0 : SLOPE * u0;
        u1 = x1.y + xr.y + a1 * we.y; u1 = u1 > 0.f ? u1 : SLOPE * u1;
        float p1 = u0 * at.x + u1 * at.y;
        u0 = x2.x + xr.x + a2 * we.x; u0 = u0 > 0.f ? u0 : SLOPE * u0;
        u1 = x2.y + xr.y + a2 * we.y; u1 = u1 > 0.f ? u1 : SLOPE * u1;
        float p2 = u0 * at.x + u1 * at.y;
        u0 = x3.x + xr.x + a3 * we.x; u0 = u0 > 0.f ? u0 : SLOPE * u0;
        u1 = x3.y + xr.y + a3 * we.y; u1 = u1 > 0.f ? u1 : SLOPE * u1;
        float p3 = u0 * at.x + u1 * at.y;
#pragma unroll
        for (int off = 16; off > 0; off >>= 1) {
            p0 += __shfl_xor_sync(0xffffffffu, p0, off);
            p1 += __shfl_xor_sync(0xffffffffu, p1, off);
            p2 += __shfl_xor_sync(0xffffffffu, p2, off);
            p3 += __shfl_xor_sync(0xffffffffu, p3, off);
        }
        float w0 = __expf(p0), w1 = __expf(p1), w2 = __expf(p2), w3 = __expf(p3);
        denA += w0 + w2; denB += w1 + w3;
        numA.x = fmaf(w0, x0.x, fmaf(w2, x2.x, numA.x));
        numA.y = fmaf(w0, x0.y, fmaf(w2, x2.y, numA.y));
        numB.x = fmaf(w1, x1.x, fmaf(w3, x3.x, numB.x));
        numB.y = fmaf(w1, x1.y, fmaf(w3, x3.y, numB.y));
    }
    for (; e < end; e++) {
        int2 er = g_edge[e];
        float a0 = __int_as_float(er.y);
        float2 x0 = *(const float2*)(g_xl2 + (size_t)er.x * EMB + c0);
        float u0, u1;
        u0 = x0.x + xr.x + a0 * we.x; u0 = u0 > 0.f ? u0 : SLOPE * u0;
        u1 = x0.y + xr.y + a0 * we.y; u1 = u1 > 0.f ? u1 : SLOPE * u1;
        float p0 = u0 * at.x + u1 * at.y;
#pragma unroll
        for (int off = 16; off > 0; off >>= 1)
            p0 += __shfl_xor_sync(0xffffffffu, p0, off);
        float w0 = __expf(p0);
        denA += w0;
        numA.x = fmaf(w0, x0.x, numA.x); numA.y = fmaf(w0, x0.y, numA.y);
    }
    float inv = 1.f / (denA + denB);
    float2 o = {(numA.x + numB.x) * inv, (numA.y + numB.y) * inv};
    *(float2*)(g_out2 + (size_t)n * EMB + c0) = o;
    atomicAdd(&ssum[c0 + 0], o.x); atomicAdd(&ssq[c0 + 0], o.x * o.x);
    atomicAdd(&ssum[c0 + 1], o.y); atomicAdd(&ssq[c0 + 1], o.y * o.y);
    __syncthreads();
    if (t < EMB) { atomicAdd(&g_bnsum2[t], ssum[t]); atomicAdd(&g_bnsq2[t], ssq[t]); }
}

// BN2(inline) + relu + node_emb + smem-staged pool sums (batch is sorted)
__global__ void k_bnapply2(const float* __restrict__ Yin, float* __restrict__ node_out,
                           const int* __restrict__ batch,
                           const float* __restrict__ gamma, const float* __restrict__ beta) {
    __shared__ float sp[256];
    __shared__ int sg[4];
    int t = threadIdx.x;
    int i = blockIdx.x * 256 + t;
    int c = i & (EMB - 1);
    int node = i >> 6;
    float mu = g_bnsum2[c] * (1.f / NN);
    float var = g_bnsq2[c] * (1.f / NN) - mu * mu;
    float sc = gamma[c] * rsqrtf(var + EPSV);
    float v = fmaf(Yin[i] - mu, sc, beta[c]);
    v = fmaxf(v, 0.f);
    node_out[i] = v;
    int g = batch[node];
    sg[t >> 6] = g;
    sp[t] = v;
    __syncthreads();
    if (sg[0] == sg[3]) {
        if (t < EMB) {
            float sum = sp[t] + sp[t + 64] + sp[t + 128] + sp[t + 192];
            atomicAdd(&g_pool[sg[0] * EMB + t], sum);
        }
    } else {
        atomicAdd(&g_pool[g * EMB + c], v);
    }
}

__global__ void k_poollogits(const float* __restrict__ Wc, const float* __restrict__ bc,
                             float* __restrict__ out) {
    int t = threadIdx.x;   // single block, 1024 threads
    for (int i = t; i < GG * EMB; i += blockDim.x) {
        int g = i >> 6;
        float dm = g_pool[i] / fmaxf(g_cnt[g], 1.f);
        g_dom[i] = dm;
        out[NCLS * GG + i] = dm;
    }
    __syncthreads();
    for (int p = t; p < GG * NCLS; p += blockDim.x) {
        int g = p / NCLS, c = p % NCLS;
        float acc = bc[c];
#pragma unroll 8
        for (int k = 0; k < EMB; k++)
            acc = fmaf(g_dom[g * EMB + k], Wc[k * NCLS + c], acc);
        out[p] = acc;
    }
}

// ---------------- host ----------------
extern "C" void kernel_launch(void* const* d_in, const int* in_sizes, int n_in,
                              void* d_out, int out_size) {
    const float* x     = (const float*)d_in[0];
    const int*   ei    = (const int*)d_in[1];
    const float* eattr = (const float*)d_in[2];
    const int*   batch = (const int*)d_in[3];
    const float* Wl1 = (const float*)d_in[4];  const float* bl1 = (const float*)d_in[5];
    const float* Wr1 = (const float*)d_in[6];  const float* br1 = (const float*)d_in[7];
    const float* We1 = (const float*)d_in[8];  const float* att1 = (const float*)d_in[9];
    // bias1 (d_in[10]) cancels exactly through BN1 -> skipped
    const float* Wl2 = (const float*)d_in[11]; const float* bl2 = (const float*)d_in[12];
    const float* Wr2 = (const float*)d_in[13]; const float* br2 = (const float*)d_in[14];
    const float* We2 = (const float*)d_in[15]; const float* att2 = (const float*)d_in[16];
    // bias2 (d_in[17]) cancels through BN2 -> skipped
    const float* gamma1 = (const float*)d_in[18]; const float* beta1 = (const float*)d_in[19];
    const float* gamma2 = (const float*)d_in[20]; const float* beta2 = (const float*)d_in[21];
    const float* Wc = (const float*)d_in[22]; const float* bc = (const float*)d_in[23];
    float* out = (float*)d_out;

    float *xr1, *out1, *xl2, *xr2, *out2;
    __half* xl1h;
    cudaGetSymbolAddress((void**)&xl1h, g_xl1h);
    cudaGetSymbolAddress((void**)&xr1, g_xr1);
    cudaGetSymbolAddress((void**)&out1, g_out1);
    cudaGetSymbolAddress((void**)&xl2, g_xl2);
    cudaGetSymbolAddress((void**)&xr2, g_xr2);
    cudaGetSymbolAddress((void**)&out2, g_out2);

    const int* src = ei;
    const int* dst = ei + EE;

    bool par = (g_side != nullptr);

    // ---- fork: gemm1 runs concurrent with CSR build ----
    if (par) {
        cudaEventRecord(g_evF, 0);
        cudaStreamWaitEvent(g_side, g_evF, 0);
    }
    k_gemm<FIN, false, true><<<dim3(391, 4), 256, 0, par ? g_side : 0>>>(
        x, Wl1, bl1, nullptr, xl1h, Wr1, br1, xr1, HID, 2, nullptr, nullptr);
    if (par) cudaEventRecord(g_evJ, g_side);

    // ---- CSR build (main stream) ----
    k_zero<<<NB, 256>>>();
    k_hist<<<(EE + 255) / 256, 256>>>(dst, eattr);
    k_scanAC<<<NB, 256>>>(batch);
    k_scatterE<<<(EE + 255) / 256, 256>>>(src, dst, eattr);

    // ---- join ----
    if (par) cudaStreamWaitEvent(0, g_evJ, 0);

    // ---- layer 1 aggregation (+BN1 stats) ----
    k_agg1<<<6250, 256>>>(We1, att1);

    // ---- layer 2 (BN1+relu fused into GEMM X load) ----
    k_gemm<HID, true, false><<<dim3(391, 2), 256>>>(
        out1, Wl2, bl2, xl2, nullptr, Wr2, br2, xr2, EMB, 1, gamma1, beta1);
    k_agg2<<<6250, 256>>>(We2, att2);

    // ---- BN2 + pooling + classifier ----
    k_bnapply2<<<(NN * EMB) / 256, 256>>>(out2, out + NCLS * GG + GG * EMB,
                                          batch, gamma2, beta2);
    k_poollogits<<<1, 1024>>>(Wc, bc, out);
}